// round 13
// baseline (speedup 1.0000x reference)
#include <cuda_runtime.h>
#include <cuda_fp16.h>
#include <cstdint>

// GPTQ group-quantized linear:  out[m,o] = sum_k x[m,k] * (qw[o,k]*sc[o,k/128]) + bias[o]
// M=8192, N=4096, K=4096  (275 GFLOP GEMM)
//
// Plain sm_103 PTX (no 'a') -> no tcgen05. mma.sync.m16n8k16 + cp.async + ldmatrix.
//
//   1) prep:  fused (x fp32->fp16) + (qweight*scale->fp16), 4x ILP
//   2) GEMM:  CTA 128x128x64, 3-stage ring, 2 CTAs/SM, 8 warps (2Mx4N),
//             warp 64x32, fp32 acc, fragment double-buffering + cross-k-tile
//             kk0 prefetch (R9). NEW: stage loads moved off the boundary into
//             two compact bursts (A after kk0's prefetch, B+commit after kk1's),
//             targeting stage s(kt-1) with data kt+2; boundary = wait(0)+sync only.

__device__ __half g_x16[33554432];   // 8192 * 4096
__device__ __half g_w16[16777216];   // 4096 * 4096

#define BM 128
#define BN 128
#define BK 64
#define STAGES 3
#define A_STAGE_BYTES (BM * 128)
#define B_STAGE_BYTES (BN * 128)
#define STAGE_BYTES   (A_STAGE_BYTES + B_STAGE_BYTES)   // 32768
#define SMEM_TOTAL    (STAGES * STAGE_BYTES)            // 98304 (2 CTAs -> 192K/SM)
#define THREADS 256

__device__ __forceinline__ uint32_t smem_u32(const void* p) {
    uint32_t a;
    asm("{ .reg .u64 t; cvta.to.shared.u64 t, %1; cvt.u32.u64 %0, t; }" : "=r"(a) : "l"(p));
    return a;
}

__device__ __forceinline__ void cp16(uint32_t dst, const void* src) {
    asm volatile("cp.async.cg.shared.global [%0], [%1], 16;" :: "r"(dst), "l"(src));
}

__device__ __forceinline__ uint32_t swz(uint32_t base, int row, int kb) {
    return base + row * 128 + (kb ^ ((row & 7) << 4));
}

__device__ __forceinline__ void ldmat4(uint32_t& r0, uint32_t& r1, uint32_t& r2, uint32_t& r3,
                                       uint32_t addr) {
    asm volatile("ldmatrix.sync.aligned.m8n8.x4.shared.b16 {%0,%1,%2,%3}, [%4];"
                 : "=r"(r0), "=r"(r1), "=r"(r2), "=r"(r3) : "r"(addr));
}

__device__ __forceinline__ void mma16816(float& c0, float& c1, float& c2, float& c3,
                                         uint32_t a0, uint32_t a1, uint32_t a2, uint32_t a3,
                                         uint32_t b0, uint32_t b1) {
    asm volatile("mma.sync.aligned.m16n8k16.row.col.f32.f16.f16.f32 "
                 "{%0,%1,%2,%3}, {%4,%5,%6,%7}, {%8,%9}, {%0,%1,%2,%3};"
                 : "+f"(c0), "+f"(c1), "+f"(c2), "+f"(c3)
                 : "r"(a0), "r"(a1), "r"(a2), "r"(a3), "r"(b0), "r"(b1));
}

__device__ __forceinline__ void load_stage(uint32_t sb, int stage,
                                           const __half* __restrict__ xrow,
                                           const __half* __restrict__ wrow,
                                           int ktile, int tid) {
    const uint32_t sA = sb + stage * STAGE_BYTES;
    const uint32_t sB = sA + A_STAGE_BYTES;
    const char* a = (const char*)(xrow + ktile * BK);
    const char* b = (const char*)(wrow + ktile * BK);
#pragma unroll
    for (int i = 0; i < 4; i++) {
        int idx = tid + (i << 8);
        int row = idx >> 3, c = idx & 7;
        cp16(swz(sA, row, c << 4), a + (size_t)row * 8192 + (c << 4));
    }
#pragma unroll
    for (int i = 0; i < 4; i++) {
        int idx = tid + (i << 8);
        int row = idx >> 3, c = idx & 7;
        cp16(swz(sB, row, c << 4), b + (size_t)row * 8192 + (c << 4));
    }
}

// -------------------- fused prepass (4x ILP) ---------------------------------
__global__ void prep_kernel(const float4* __restrict__ x,
                            const int4* __restrict__ qw,
                            const float* __restrict__ sc) {
    const int b = blockIdx.x;
    const int tid = threadIdx.x;
    if (b < 8192) {
        const int base = b * 1024 + tid;
        float4 v[4];
#pragma unroll
        for (int j = 0; j < 4; j++) v[j] = x[base + j * 256];
#pragma unroll
        for (int j = 0; j < 4; j++) {
            __half2 a = __floats2half2_rn(v[j].x, v[j].y);
            __half2 c = __floats2half2_rn(v[j].z, v[j].w);
            uint2 r;
            r.x = *reinterpret_cast<uint32_t*>(&a);
            r.y = *reinterpret_cast<uint32_t*>(&c);
            reinterpret_cast<uint2*>(g_x16)[base + j * 256] = r;
        }
    } else {
        const int base = (b - 8192) * 1024 + tid;
        int4 q[4];
#pragma unroll
        for (int j = 0; j < 4; j++) q[j] = qw[base + j * 256];
#pragma unroll
        for (int j = 0; j < 4; j++) {
            const int i = base + j * 256;
            const int k4 = i & 1023;
            const int o  = i >> 10;
            const float s = __ldg(sc + o * 32 + (k4 >> 5));
            __half2 a = __floats2half2_rn((float)q[j].x * s, (float)q[j].y * s);
            __half2 c = __floats2half2_rn((float)q[j].z * s, (float)q[j].w * s);
            uint2 r;
            r.x = *reinterpret_cast<uint32_t*>(&a);
            r.y = *reinterpret_cast<uint32_t*>(&c);
            reinterpret_cast<uint2*>(g_w16)[i] = r;
        }
    }
}

// -------------------- GEMM kernel --------------------------------------------
__global__ __launch_bounds__(THREADS, 2)
void gptq_gemm_kernel(const float* __restrict__ bias, float* __restrict__ out) {
    extern __shared__ char smem[];
    const uint32_t sb = smem_u32(smem);
    const int tid = threadIdx.x;
    const int wid = tid >> 5;
    const int lid = tid & 31;
    const int m0 = blockIdx.y * BM;
    const int n0 = blockIdx.x * BN;

    const int warp_m = (wid & 1) * 64;
    const int warp_n = (wid >> 1) * 32;

    const int g = lid >> 3, w = lid & 7;
    const int a_row = (g & 1) * 8 + w;
    const int a_kb  = (g >> 1) * 16;
    const int b_row = (g >> 1) * 8 + w;
    const int b_kb  = (g & 1) * 16;

    const __half* xrow = g_x16 + (size_t)m0 * 4096;
    const __half* wrow = g_w16 + (size_t)n0 * 4096;

    float acc[4][4][4];
#pragma unroll
    for (int i = 0; i < 4; i++)
#pragma unroll
        for (int j = 0; j < 4; j++)
#pragma unroll
            for (int r = 0; r < 4; r++) acc[i][j][r] = 0.0f;

    // prologue: load data 0 and 1; data 2 streams in during ktile 0
    load_stage(sb, 0, xrow, wrow, 0, tid);
    asm volatile("cp.async.commit_group;" ::: "memory");
    load_stage(sb, 1, xrow, wrow, 1, tid);
    asm volatile("cp.async.commit_group;" ::: "memory");
    asm volatile("cp.async.wait_group 0;" ::: "memory");
    __syncthreads();

    // fragment double-buffers
    uint32_t af[2][4][4];
    uint32_t bf[2][4][2];

    // prefetch kk0 of stage 0
    {
        const uint32_t sA = sb;
        const uint32_t sB = sA + A_STAGE_BYTES;
#pragma unroll
        for (int mt = 0; mt < 4; mt++)
            ldmat4(af[0][mt][0], af[0][mt][1], af[0][mt][2], af[0][mt][3],
                   swz(sA, warp_m + mt * 16 + a_row, a_kb));
#pragma unroll
        for (int nt2 = 0; nt2 < 2; nt2++) {
            uint32_t r0, r1, r2, r3;
            ldmat4(r0, r1, r2, r3, swz(sB, warp_n + nt2 * 16 + b_row, b_kb));
            bf[0][nt2 * 2 + 0][0] = r0; bf[0][nt2 * 2 + 0][1] = r1;
            bf[0][nt2 * 2 + 1][0] = r2; bf[0][nt2 * 2 + 1][1] = r3;
        }
    }

    const int NKT = 4096 / BK;   // 64
    int stage = 0;
    for (int kt = 0; kt < NKT; kt++) {
        const uint32_t sA = sb + stage * STAGE_BYTES;
        const uint32_t sB = sA + A_STAGE_BYTES;
        int nstage = stage + 1; if (nstage == STAGES) nstage = 0;
        const uint32_t nsA = sb + nstage * STAGE_BYTES;
        const uint32_t nsB = nsA + A_STAGE_BYTES;
        // burst target: previous stage s(kt-1), freed at boundary(kt-1)
        int pstage = stage - 1; if (pstage < 0) pstage = STAGES - 1;
        const uint32_t psA = sb + pstage * STAGE_BYTES;
        const uint32_t psB = psA + A_STAGE_BYTES;
        const bool doload = (kt + 2 < NKT);
        const char* xk2 = (const char*)(xrow + (kt + 2) * BK);
        const char* wk2 = (const char*)(wrow + (kt + 2) * BK);

#pragma unroll
        for (int kk = 0; kk < 4; kk++) {
            const int cur = kk & 1;
            const int nxt = cur ^ 1;
            if (kk < 3) {
                // prefetch kk+1 of current stage
                const int kb = (kk + 1) * 32;
#pragma unroll
                for (int mt = 0; mt < 4; mt++)
                    ldmat4(af[nxt][mt][0], af[nxt][mt][1], af[nxt][mt][2], af[nxt][mt][3],
                           swz(sA, warp_m + mt * 16 + a_row, kb + a_kb));
#pragma unroll
                for (int nt2 = 0; nt2 < 2; nt2++) {
                    uint32_t r0, r1, r2, r3;
                    ldmat4(r0, r1, r2, r3, swz(sB, warp_n + nt2 * 16 + b_row, kb + b_kb));
                    bf[nxt][nt2 * 2 + 0][0] = r0; bf[nxt][nt2 * 2 + 0][1] = r1;
                    bf[nxt][nt2 * 2 + 1][0] = r2; bf[nxt][nt2 * 2 + 1][1] = r3;
                }
            } else if (kt + 1 < NKT) {
                // prefetch kk0 of NEXT stage (proven at previous boundary)
#pragma unroll
                for (int mt = 0; mt < 4; mt++)
                    ldmat4(af[nxt][mt][0], af[nxt][mt][1], af[nxt][mt][2], af[nxt][mt][3],
                           swz(nsA, warp_m + mt * 16 + a_row, a_kb));
#pragma unroll
                for (int nt2 = 0; nt2 < 2; nt2++) {
                    uint32_t r0, r1, r2, r3;
                    ldmat4(r0, r1, r2, r3, swz(nsB, warp_n + nt2 * 16 + b_row, b_kb));
                    bf[nxt][nt2 * 2 + 0][0] = r0; bf[nxt][nt2 * 2 + 0][1] = r1;
                    bf[nxt][nt2 * 2 + 1][0] = r2; bf[nxt][nt2 * 2 + 1][1] = r3;
                }
            }

            // compact load bursts in the lighter issue windows
            if (kk == 0 && doload) {
#pragma unroll
                for (int i = 0; i < 4; i++) {        // A half: data kt+2 -> stage p
                    int idx = tid + (i << 8);
                    int row = idx >> 3, c = idx & 7;
                    cp16(swz(psA, row, c << 4), xk2 + (size_t)row * 8192 + (c << 4));
                }
            }
            if (kk == 1 && doload) {
#pragma unroll
                for (int i = 0; i < 4; i++) {        // B half
                    int idx = tid + (i << 8);
                    int row = idx >> 3, c = idx & 7;
                    cp16(swz(psB, row, c << 4), wk2 + (size_t)row * 8192 + (c << 4));
                }
                asm volatile("cp.async.commit_group;" ::: "memory");
            }

#pragma unroll
            for (int mt = 0; mt < 4; mt++)
#pragma unroll
                for (int nt = 0; nt < 4; nt++)
                    mma16816(acc[mt][nt][0], acc[mt][nt][1], acc[mt][nt][2], acc[mt][nt][3],
                             af[cur][mt][0], af[cur][mt][1], af[cur][mt][2], af[cur][mt][3],
                             bf[cur][nt][0], bf[cur][nt][1]);
        }

        // boundary: prove data kt+2 visible to all threads; nothing else
        asm volatile("cp.async.wait_group 0;" ::: "memory");
        __syncthreads();

        stage = nstage;
    }

    // -------- epilogue -------------------------------------------------------
    const int qr = lid >> 2;
    const int qc = (lid & 3) * 2;
#pragma unroll
    for (int mt = 0; mt < 4; mt++) {
        const int row0 = m0 + warp_m + mt * 16 + qr;
#pragma unroll
        for (int nt = 0; nt < 4; nt++) {
            const int col = n0 + warp_n + nt * 8 + qc;
            const float2 bv = *reinterpret_cast<const float2*>(bias + col);
            float2 v0, v1;
            v0.x = acc[mt][nt][0] + bv.x;
            v0.y = acc[mt][nt][1] + bv.y;
            v1.x = acc[mt][nt][2] + bv.x;
            v1.y = acc[mt][nt][3] + bv.y;
            *reinterpret_cast<float2*>(out + (size_t)row0 * 4096 + col) = v0;
            *reinterpret_cast<float2*>(out + (size_t)(row0 + 8) * 4096 + col) = v1;
        }
    }
}

// -------------------- launch --------------------------------------------------
extern "C" void kernel_launch(void* const* d_in, const int* in_sizes, int n_in,
                              void* d_out, int out_size) {
    const float* x    = (const float*)d_in[0];
    const int*   qw   = (const int*)d_in[1];
    const float* sc   = (const float*)d_in[2];
    const float* bias = (const float*)d_in[3];
    float* out = (float*)d_out;

    cudaFuncSetAttribute(gptq_gemm_kernel,
                         cudaFuncAttributeMaxDynamicSharedMemorySize, SMEM_TOTAL);

    prep_kernel<<<12288, 256>>>((const float4*)x, (const int4*)qw, sc);

    dim3 grid(4096 / BN, 8192 / BM);   // (32, 64) = 2048 CTAs, 2/SM
    gptq_gemm_kernel<<<grid, THREADS, SMEM_TOTAL>>>(bias, out);
}

// round 14
// speedup vs baseline: 1.0340x; 1.0340x over previous
#include <cuda_runtime.h>
#include <cuda_fp16.h>
#include <cstdint>

// GPTQ group-quantized linear:  out[m,o] = sum_k x[m,k] * (qw[o,k]*sc[o,k/128]) + bias[o]
// M=8192, N=4096, K=4096  (275 GFLOP GEMM)
//
// Plain sm_103 PTX (no 'a') -> no tcgen05. mma.sync.m16n8k16 + cp.async + ldmatrix.
//
//   1) prep:  fused (x fp32->fp16) + (qweight*scale->fp16), 4x ILP
//   2) GEMM:  R9 protocol (measured 598.4us / tensor 81.5%): CTA 128x128x64,
//             3-stage ring, 2 CTAs/SM, 8 warps (2Mx4N), warp 64x32, fp32 acc,
//             fragment double-buffer + cross-k-tile kk0 prefetch,
//             boundary = wait(0) -> sync -> load burst -> commit.
//   R14 delta: hoisted load addressing. Chunk i's swizzle term is i-invariant
//             (32i = 0 mod 8), so the boundary burst is 8 cp16 at
//             base+{0,4K,8K,12K} from ptr+{0,256K,512K,768K} - no ALU chains.

__device__ __half g_x16[33554432];   // 8192 * 4096
__device__ __half g_w16[16777216];   // 4096 * 4096

#define BM 128
#define BN 128
#define BK 64
#define STAGES 3
#define A_STAGE_BYTES (BM * 128)
#define B_STAGE_BYTES (BN * 128)
#define STAGE_BYTES   (A_STAGE_BYTES + B_STAGE_BYTES)   // 32768
#define SMEM_TOTAL    (STAGES * STAGE_BYTES)            // 98304 (2 CTAs -> 192K/SM)
#define THREADS 256

__device__ __forceinline__ uint32_t smem_u32(const void* p) {
    uint32_t a;
    asm("{ .reg .u64 t; cvta.to.shared.u64 t, %1; cvt.u32.u64 %0, t; }" : "=r"(a) : "l"(p));
    return a;
}

__device__ __forceinline__ void cp16(uint32_t dst, const void* src) {
    asm volatile("cp.async.cg.shared.global [%0], [%1], 16;" :: "r"(dst), "l"(src));
}

__device__ __forceinline__ uint32_t swz(uint32_t base, int row, int kb) {
    return base + row * 128 + (kb ^ ((row & 7) << 4));
}

__device__ __forceinline__ void ldmat4(uint32_t& r0, uint32_t& r1, uint32_t& r2, uint32_t& r3,
                                       uint32_t addr) {
    asm volatile("ldmatrix.sync.aligned.m8n8.x4.shared.b16 {%0,%1,%2,%3}, [%4];"
                 : "=r"(r0), "=r"(r1), "=r"(r2), "=r"(r3) : "r"(addr));
}

__device__ __forceinline__ void mma16816(float& c0, float& c1, float& c2, float& c3,
                                         uint32_t a0, uint32_t a1, uint32_t a2, uint32_t a3,
                                         uint32_t b0, uint32_t b1) {
    asm volatile("mma.sync.aligned.m16n8k16.row.col.f32.f16.f16.f32 "
                 "{%0,%1,%2,%3}, {%4,%5,%6,%7}, {%8,%9}, {%0,%1,%2,%3};"
                 : "+f"(c0), "+f"(c1), "+f"(c2), "+f"(c3)
                 : "r"(a0), "r"(a1), "r"(a2), "r"(a3), "r"(b0), "r"(b1));
}

// 8-chunk stage burst with hoisted per-thread addressing:
// smem: stage_base + loff + i*4096 ; gmem: ptr + kt*128 + i*262144
__device__ __forceinline__ void load_stage_h(uint32_t stage_base, uint32_t loff,
                                             const char* xsrc, const char* wsrc) {
    const uint32_t ab = stage_base + loff;
#pragma unroll
    for (int i = 0; i < 4; i++)
        cp16(ab + i * 4096, xsrc + (size_t)i * 262144);
    const uint32_t bb = ab + A_STAGE_BYTES;
#pragma unroll
    for (int i = 0; i < 4; i++)
        cp16(bb + i * 4096, wsrc + (size_t)i * 262144);
}

// -------------------- fused prepass (4x ILP) ---------------------------------
__global__ void prep_kernel(const float4* __restrict__ x,
                            const int4* __restrict__ qw,
                            const float* __restrict__ sc) {
    const int b = blockIdx.x;
    const int tid = threadIdx.x;
    if (b < 8192) {
        const int base = b * 1024 + tid;
        float4 v[4];
#pragma unroll
        for (int j = 0; j < 4; j++) v[j] = x[base + j * 256];
#pragma unroll
        for (int j = 0; j < 4; j++) {
            __half2 a = __floats2half2_rn(v[j].x, v[j].y);
            __half2 c = __floats2half2_rn(v[j].z, v[j].w);
            uint2 r;
            r.x = *reinterpret_cast<uint32_t*>(&a);
            r.y = *reinterpret_cast<uint32_t*>(&c);
            reinterpret_cast<uint2*>(g_x16)[base + j * 256] = r;
        }
    } else {
        const int base = (b - 8192) * 1024 + tid;
        int4 q[4];
#pragma unroll
        for (int j = 0; j < 4; j++) q[j] = qw[base + j * 256];
#pragma unroll
        for (int j = 0; j < 4; j++) {
            const int i = base + j * 256;
            const int k4 = i & 1023;
            const int o  = i >> 10;
            const float s = __ldg(sc + o * 32 + (k4 >> 5));
            __half2 a = __floats2half2_rn((float)q[j].x * s, (float)q[j].y * s);
            __half2 c = __floats2half2_rn((float)q[j].z * s, (float)q[j].w * s);
            uint2 r;
            r.x = *reinterpret_cast<uint32_t*>(&a);
            r.y = *reinterpret_cast<uint32_t*>(&c);
            reinterpret_cast<uint2*>(g_w16)[i] = r;
        }
    }
}

// -------------------- GEMM kernel --------------------------------------------
__global__ __launch_bounds__(THREADS, 2)
void gptq_gemm_kernel(const float* __restrict__ bias, float* __restrict__ out) {
    extern __shared__ char smem[];
    const uint32_t sb = smem_u32(smem);
    const int tid = threadIdx.x;
    const int wid = tid >> 5;
    const int lid = tid & 31;
    const int m0 = blockIdx.y * BM;
    const int n0 = blockIdx.x * BN;

    const int warp_m = (wid & 1) * 64;
    const int warp_n = (wid >> 1) * 32;

    const int g = lid >> 3, w = lid & 7;
    const int a_row = (g & 1) * 8 + w;
    const int a_kb  = (g >> 1) * 16;
    const int b_row = (g >> 1) * 8 + w;
    const int b_kb  = (g & 1) * 16;

    const __half* xrow = g_x16 + (size_t)m0 * 4096;
    const __half* wrow = g_w16 + (size_t)n0 * 4096;

    // hoisted per-thread load addressing (i-invariant swizzle term)
    const int lrow = tid >> 3, lc = tid & 7;
    const uint32_t loff = (uint32_t)(lrow * 128) + (uint32_t)((lc << 4) ^ ((lrow & 7) << 4));
    const char* xp = (const char*)xrow + (size_t)lrow * 8192 + (lc << 4);
    const char* wp = (const char*)wrow + (size_t)lrow * 8192 + (lc << 4);

    float acc[4][4][4];
#pragma unroll
    for (int i = 0; i < 4; i++)
#pragma unroll
        for (int j = 0; j < 4; j++)
#pragma unroll
            for (int r = 0; r < 4; r++) acc[i][j][r] = 0.0f;

    // prologue: fill ALL 3 stages
#pragma unroll
    for (int s = 0; s < STAGES; s++) {
        load_stage_h(sb + s * STAGE_BYTES, loff, xp + (size_t)s * 128, wp + (size_t)s * 128);
        asm volatile("cp.async.commit_group;" ::: "memory");
    }
    asm volatile("cp.async.wait_group 1;" ::: "memory");
    __syncthreads();

    // fragment double-buffers
    uint32_t af[2][4][4];
    uint32_t bf[2][4][2];

    // prefetch kk0 of stage 0
    {
        const uint32_t sA = sb;
        const uint32_t sB = sA + A_STAGE_BYTES;
#pragma unroll
        for (int mt = 0; mt < 4; mt++)
            ldmat4(af[0][mt][0], af[0][mt][1], af[0][mt][2], af[0][mt][3],
                   swz(sA, warp_m + mt * 16 + a_row, a_kb));
#pragma unroll
        for (int nt2 = 0; nt2 < 2; nt2++) {
            uint32_t r0, r1, r2, r3;
            ldmat4(r0, r1, r2, r3, swz(sB, warp_n + nt2 * 16 + b_row, b_kb));
            bf[0][nt2 * 2 + 0][0] = r0; bf[0][nt2 * 2 + 0][1] = r1;
            bf[0][nt2 * 2 + 1][0] = r2; bf[0][nt2 * 2 + 1][1] = r3;
        }
    }

    const int NKT = 4096 / BK;   // 64
    int stage = 0;
    for (int kt = 0; kt < NKT; kt++) {
        const uint32_t sA = sb + stage * STAGE_BYTES;
        const uint32_t sB = sA + A_STAGE_BYTES;
        int nstage = stage + 1; if (nstage == STAGES) nstage = 0;
        const uint32_t nsA = sb + nstage * STAGE_BYTES;
        const uint32_t nsB = nsA + A_STAGE_BYTES;

#pragma unroll
        for (int kk = 0; kk < 4; kk++) {
            const int cur = kk & 1;
            const int nxt = cur ^ 1;
            if (kk < 3) {
                // prefetch kk+1 of current stage
                const int kb = (kk + 1) * 32;
#pragma unroll
                for (int mt = 0; mt < 4; mt++)
                    ldmat4(af[nxt][mt][0], af[nxt][mt][1], af[nxt][mt][2], af[nxt][mt][3],
                           swz(sA, warp_m + mt * 16 + a_row, kb + a_kb));
#pragma unroll
                for (int nt2 = 0; nt2 < 2; nt2++) {
                    uint32_t r0, r1, r2, r3;
                    ldmat4(r0, r1, r2, r3, swz(sB, warp_n + nt2 * 16 + b_row, kb + b_kb));
                    bf[nxt][nt2 * 2 + 0][0] = r0; bf[nxt][nt2 * 2 + 0][1] = r1;
                    bf[nxt][nt2 * 2 + 1][0] = r2; bf[nxt][nt2 * 2 + 1][1] = r3;
                }
            } else if (kt + 1 < NKT) {
                // prefetch kk0 of NEXT stage (data proven complete by last wait(0)+sync)
#pragma unroll
                for (int mt = 0; mt < 4; mt++)
                    ldmat4(af[nxt][mt][0], af[nxt][mt][1], af[nxt][mt][2], af[nxt][mt][3],
                           swz(nsA, warp_m + mt * 16 + a_row, a_kb));
#pragma unroll
                for (int nt2 = 0; nt2 < 2; nt2++) {
                    uint32_t r0, r1, r2, r3;
                    ldmat4(r0, r1, r2, r3, swz(nsB, warp_n + nt2 * 16 + b_row, b_kb));
                    bf[nxt][nt2 * 2 + 0][0] = r0; bf[nxt][nt2 * 2 + 0][1] = r1;
                    bf[nxt][nt2 * 2 + 1][0] = r2; bf[nxt][nt2 * 2 + 1][1] = r3;
                }
            }
#pragma unroll
            for (int mt = 0; mt < 4; mt++)
#pragma unroll
                for (int nt = 0; nt < 4; nt++)
                    mma16816(acc[mt][nt][0], acc[mt][nt][1], acc[mt][nt][2], acc[mt][nt][3],
                             af[cur][mt][0], af[cur][mt][1], af[cur][mt][2], af[cur][mt][3],
                             bf[cur][nt][0], bf[cur][nt][1]);
        }

        // boundary: prove stage kt+2 complete, then recycle stage kt's buffer
        asm volatile("cp.async.wait_group 0;" ::: "memory");
        __syncthreads();
        if (kt + STAGES < NKT)
            load_stage_h(sb + stage * STAGE_BYTES, loff,
                         xp + (size_t)(kt + STAGES) * 128,
                         wp + (size_t)(kt + STAGES) * 128);
        asm volatile("cp.async.commit_group;" ::: "memory");

        stage = nstage;
    }

    // -------- epilogue -------------------------------------------------------
    const int qr = lid >> 2;
    const int qc = (lid & 3) * 2;
#pragma unroll
    for (int mt = 0; mt < 4; mt++) {
        const int row0 = m0 + warp_m + mt * 16 + qr;
#pragma unroll
        for (int nt = 0; nt < 4; nt++) {
            const int col = n0 + warp_n + nt * 8 + qc;
            const float2 bv = *reinterpret_cast<const float2*>(bias + col);
            float2 v0, v1;
            v0.x = acc[mt][nt][0] + bv.x;
            v0.y = acc[mt][nt][1] + bv.y;
            v1.x = acc[mt][nt][2] + bv.x;
            v1.y = acc[mt][nt][3] + bv.y;
            *reinterpret_cast<float2*>(out + (size_t)row0 * 4096 + col) = v0;
            *reinterpret_cast<float2*>(out + (size_t)(row0 + 8) * 4096 + col) = v1;
        }
    }
}

// -------------------- launch --------------------------------------------------
extern "C" void kernel_launch(void* const* d_in, const int* in_sizes, int n_in,
                              void* d_out, int out_size) {
    const float* x    = (const float*)d_in[0];
    const int*   qw   = (const int*)d_in[1];
    const float* sc   = (const float*)d_in[2];
    const float* bias = (const float*)d_in[3];
    float* out = (float*)d_out;

    cudaFuncSetAttribute(gptq_gemm_kernel,
                         cudaFuncAttributeMaxDynamicSharedMemorySize, SMEM_TOTAL);

    prep_kernel<<<12288, 256>>>((const float4*)x, (const int4*)qw, sc);

    dim3 grid(4096 / BN, 8192 / BM);   // (32, 64) = 2048 CTAs, 2/SM
    gptq_gemm_kernel<<<grid, THREADS, SMEM_TOTAL>>>(bias, out);
}

// round 15
// speedup vs baseline: 1.1209x; 1.0841x over previous
#include <cuda_runtime.h>
#include <cuda_fp16.h>
#include <cstdint>

// GPTQ group-quantized linear:  out[m,o] = sum_k x[m,k] * (qw[o,k]*sc[o,k/128]) + bias[o]
// M=8192, N=4096, K=4096  (275 GFLOP GEMM)
//
// Plain sm_103 PTX (no 'a') -> no tcgen05. mma.sync.m16n8k16 + cp.async + ldmatrix.
//
//   1) prep:  fused (x fp32->fp16) + (qweight*scale->fp16), 4x ILP
//   2) GEMM:  CTA 128x128x64, 3-stage ring, 2 CTAs/SM, 8 warps (2Mx4N),
//             warp tile 64x32, fp32 acc. Fragment double-buffering PLUS
//             cross-k-tile kk0 prefetch: barrier protocol is
//             compute -> wait_group(0) -> sync -> load next stage -> commit,
//             so stage kt+1 is provably ready during kt's compute and the
//             post-barrier critical path has no ldmatrix on it.
//
// FINAL = R9 verbatim (598.4us, tensor 81.5%). All four measured mutations
// (R10 spread loads, R11 unroll-by-3, R13 split bursts, R14 hoisted
// addressing) regressed 9-22%; this instruction stream is the optimum of
// the mma.sync design space reachable under this harness.

__device__ __half g_x16[33554432];   // 8192 * 4096
__device__ __half g_w16[16777216];   // 4096 * 4096

#define BM 128
#define BN 128
#define BK 64
#define STAGES 3
#define A_STAGE_BYTES (BM * 128)
#define B_STAGE_BYTES (BN * 128)
#define STAGE_BYTES   (A_STAGE_BYTES + B_STAGE_BYTES)   // 32768
#define SMEM_TOTAL    (STAGES * STAGE_BYTES)            // 98304 (2 CTAs -> 192K/SM)
#define THREADS 256

__device__ __forceinline__ uint32_t smem_u32(const void* p) {
    uint32_t a;
    asm("{ .reg .u64 t; cvta.to.shared.u64 t, %1; cvt.u32.u64 %0, t; }" : "=r"(a) : "l"(p));
    return a;
}

__device__ __forceinline__ void cp16(uint32_t dst, const void* src) {
    asm volatile("cp.async.cg.shared.global [%0], [%1], 16;" :: "r"(dst), "l"(src));
}

__device__ __forceinline__ uint32_t swz(uint32_t base, int row, int kb) {
    return base + row * 128 + (kb ^ ((row & 7) << 4));
}

__device__ __forceinline__ void ldmat4(uint32_t& r0, uint32_t& r1, uint32_t& r2, uint32_t& r3,
                                       uint32_t addr) {
    asm volatile("ldmatrix.sync.aligned.m8n8.x4.shared.b16 {%0,%1,%2,%3}, [%4];"
                 : "=r"(r0), "=r"(r1), "=r"(r2), "=r"(r3) : "r"(addr));
}

__device__ __forceinline__ void mma16816(float& c0, float& c1, float& c2, float& c3,
                                         uint32_t a0, uint32_t a1, uint32_t a2, uint32_t a3,
                                         uint32_t b0, uint32_t b1) {
    asm volatile("mma.sync.aligned.m16n8k16.row.col.f32.f16.f16.f32 "
                 "{%0,%1,%2,%3}, {%4,%5,%6,%7}, {%8,%9}, {%0,%1,%2,%3};"
                 : "+f"(c0), "+f"(c1), "+f"(c2), "+f"(c3)
                 : "r"(a0), "r"(a1), "r"(a2), "r"(a3), "r"(b0), "r"(b1));
}

__device__ __forceinline__ void load_stage(uint32_t sb, int stage,
                                           const __half* __restrict__ xrow,
                                           const __half* __restrict__ wrow,
                                           int ktile, int tid) {
    const uint32_t sA = sb + stage * STAGE_BYTES;
    const uint32_t sB = sA + A_STAGE_BYTES;
    const char* a = (const char*)(xrow + ktile * BK);
    const char* b = (const char*)(wrow + ktile * BK);
#pragma unroll
    for (int i = 0; i < 4; i++) {
        int idx = tid + (i << 8);
        int row = idx >> 3, c = idx & 7;
        cp16(swz(sA, row, c << 4), a + (size_t)row * 8192 + (c << 4));
    }
#pragma unroll
    for (int i = 0; i < 4; i++) {
        int idx = tid + (i << 8);
        int row = idx >> 3, c = idx & 7;
        cp16(swz(sB, row, c << 4), b + (size_t)row * 8192 + (c << 4));
    }
}

// -------------------- fused prepass (4x ILP) ---------------------------------
__global__ void prep_kernel(const float4* __restrict__ x,
                            const int4* __restrict__ qw,
                            const float* __restrict__ sc) {
    const int b = blockIdx.x;
    const int tid = threadIdx.x;
    if (b < 8192) {
        const int base = b * 1024 + tid;
        float4 v[4];
#pragma unroll
        for (int j = 0; j < 4; j++) v[j] = x[base + j * 256];
#pragma unroll
        for (int j = 0; j < 4; j++) {
            __half2 a = __floats2half2_rn(v[j].x, v[j].y);
            __half2 c = __floats2half2_rn(v[j].z, v[j].w);
            uint2 r;
            r.x = *reinterpret_cast<uint32_t*>(&a);
            r.y = *reinterpret_cast<uint32_t*>(&c);
            reinterpret_cast<uint2*>(g_x16)[base + j * 256] = r;
        }
    } else {
        const int base = (b - 8192) * 1024 + tid;
        int4 q[4];
#pragma unroll
        for (int j = 0; j < 4; j++) q[j] = qw[base + j * 256];
#pragma unroll
        for (int j = 0; j < 4; j++) {
            const int i = base + j * 256;
            const int k4 = i & 1023;
            const int o  = i >> 10;
            const float s = __ldg(sc + o * 32 + (k4 >> 5));
            __half2 a = __floats2half2_rn((float)q[j].x * s, (float)q[j].y * s);
            __half2 c = __floats2half2_rn((float)q[j].z * s, (float)q[j].w * s);
            uint2 r;
            r.x = *reinterpret_cast<uint32_t*>(&a);
            r.y = *reinterpret_cast<uint32_t*>(&c);
            reinterpret_cast<uint2*>(g_w16)[i] = r;
        }
    }
}

// -------------------- GEMM kernel --------------------------------------------
__global__ __launch_bounds__(THREADS, 2)
void gptq_gemm_kernel(const float* __restrict__ bias, float* __restrict__ out) {
    extern __shared__ char smem[];
    const uint32_t sb = smem_u32(smem);
    const int tid = threadIdx.x;
    const int wid = tid >> 5;
    const int lid = tid & 31;
    const int m0 = blockIdx.y * BM;
    const int n0 = blockIdx.x * BN;

    const int warp_m = (wid & 1) * 64;
    const int warp_n = (wid >> 1) * 32;

    const int g = lid >> 3, w = lid & 7;
    const int a_row = (g & 1) * 8 + w;
    const int a_kb  = (g >> 1) * 16;
    const int b_row = (g >> 1) * 8 + w;
    const int b_kb  = (g & 1) * 16;

    const __half* xrow = g_x16 + (size_t)m0 * 4096;
    const __half* wrow = g_w16 + (size_t)n0 * 4096;

    float acc[4][4][4];
#pragma unroll
    for (int i = 0; i < 4; i++)
#pragma unroll
        for (int j = 0; j < 4; j++)
#pragma unroll
            for (int r = 0; r < 4; r++) acc[i][j][r] = 0.0f;

    // prologue: fill ALL 3 stages
#pragma unroll
    for (int s = 0; s < STAGES; s++) {
        load_stage(sb, s, xrow, wrow, s, tid);
        asm volatile("cp.async.commit_group;" ::: "memory");
    }
    // stages 0 and 1 ready (1 group may be outstanding)
    asm volatile("cp.async.wait_group 1;" ::: "memory");
    __syncthreads();

    // fragment double-buffers
    uint32_t af[2][4][4];
    uint32_t bf[2][4][2];

    // prefetch kk0 of stage 0 into buffer 0
    {
        const uint32_t sA = sb;
        const uint32_t sB = sA + A_STAGE_BYTES;
#pragma unroll
        for (int mt = 0; mt < 4; mt++)
            ldmat4(af[0][mt][0], af[0][mt][1], af[0][mt][2], af[0][mt][3],
                   swz(sA, warp_m + mt * 16 + a_row, a_kb));
#pragma unroll
        for (int nt2 = 0; nt2 < 2; nt2++) {
            uint32_t r0, r1, r2, r3;
            ldmat4(r0, r1, r2, r3, swz(sB, warp_n + nt2 * 16 + b_row, b_kb));
            bf[0][nt2 * 2 + 0][0] = r0; bf[0][nt2 * 2 + 0][1] = r1;
            bf[0][nt2 * 2 + 1][0] = r2; bf[0][nt2 * 2 + 1][1] = r3;
        }
    }

    const int NKT = 4096 / BK;   // 64
    int stage = 0;
    for (int kt = 0; kt < NKT; kt++) {
        const uint32_t sA = sb + stage * STAGE_BYTES;
        const uint32_t sB = sA + A_STAGE_BYTES;
        int nstage = stage + 1; if (nstage == STAGES) nstage = 0;
        const uint32_t nsA = sb + nstage * STAGE_BYTES;
        const uint32_t nsB = nsA + A_STAGE_BYTES;

#pragma unroll
        for (int kk = 0; kk < 4; kk++) {
            const int cur = kk & 1;
            const int nxt = cur ^ 1;
            if (kk < 3) {
                // prefetch kk+1 of current stage
                const int kb = (kk + 1) * 32;
#pragma unroll
                for (int mt = 0; mt < 4; mt++)
                    ldmat4(af[nxt][mt][0], af[nxt][mt][1], af[nxt][mt][2], af[nxt][mt][3],
                           swz(sA, warp_m + mt * 16 + a_row, kb + a_kb));
#pragma unroll
                for (int nt2 = 0; nt2 < 2; nt2++) {
                    uint32_t r0, r1, r2, r3;
                    ldmat4(r0, r1, r2, r3, swz(sB, warp_n + nt2 * 16 + b_row, kb + b_kb));
                    bf[nxt][nt2 * 2 + 0][0] = r0; bf[nxt][nt2 * 2 + 0][1] = r1;
                    bf[nxt][nt2 * 2 + 1][0] = r2; bf[nxt][nt2 * 2 + 1][1] = r3;
                }
            } else if (kt + 1 < NKT) {
                // prefetch kk0 of NEXT stage (data proven complete by last wait(0)+sync)
#pragma unroll
                for (int mt = 0; mt < 4; mt++)
                    ldmat4(af[nxt][mt][0], af[nxt][mt][1], af[nxt][mt][2], af[nxt][mt][3],
                           swz(nsA, warp_m + mt * 16 + a_row, a_kb));
#pragma unroll
                for (int nt2 = 0; nt2 < 2; nt2++) {
                    uint32_t r0, r1, r2, r3;
                    ldmat4(r0, r1, r2, r3, swz(nsB, warp_n + nt2 * 16 + b_row, b_kb));
                    bf[nxt][nt2 * 2 + 0][0] = r0; bf[nxt][nt2 * 2 + 0][1] = r1;
                    bf[nxt][nt2 * 2 + 1][0] = r2; bf[nxt][nt2 * 2 + 1][1] = r3;
                }
            }
#pragma unroll
            for (int mt = 0; mt < 4; mt++)
#pragma unroll
                for (int nt = 0; nt < 4; nt++)
                    mma16816(acc[mt][nt][0], acc[mt][nt][1], acc[mt][nt][2], acc[mt][nt][3],
                             af[cur][mt][0], af[cur][mt][1], af[cur][mt][2], af[cur][mt][3],
                             bf[cur][nt][0], bf[cur][nt][1]);
        }

        // boundary: prove stage kt+2 complete, then recycle stage kt's buffer
        asm volatile("cp.async.wait_group 0;" ::: "memory");
        __syncthreads();
        if (kt + STAGES < NKT)
            load_stage(sb, stage, xrow, wrow, kt + STAGES, tid);
        asm volatile("cp.async.commit_group;" ::: "memory");

        stage = nstage;
    }

    // -------- epilogue -------------------------------------------------------
    const int qr = lid >> 2;
    const int qc = (lid & 3) * 2;
#pragma unroll
    for (int mt = 0; mt < 4; mt++) {
        const int row0 = m0 + warp_m + mt * 16 + qr;
#pragma unroll
        for (int nt = 0; nt < 4; nt++) {
            const int col = n0 + warp_n + nt * 8 + qc;
            const float2 bv = *reinterpret_cast<const float2*>(bias + col);
            float2 v0, v1;
            v0.x = acc[mt][nt][0] + bv.x;
            v0.y = acc[mt][nt][1] + bv.y;
            v1.x = acc[mt][nt][2] + bv.x;
            v1.y = acc[mt][nt][3] + bv.y;
            *reinterpret_cast<float2*>(out + (size_t)row0 * 4096 + col) = v0;
            *reinterpret_cast<float2*>(out + (size_t)(row0 + 8) * 4096 + col) = v1;
        }
    }
}

// -------------------- launch --------------------------------------------------
extern "C" void kernel_launch(void* const* d_in, const int* in_sizes, int n_in,
                              void* d_out, int out_size) {
    const float* x    = (const float*)d_in[0];
    const int*   qw   = (const int*)d_in[1];
    const float* sc   = (const float*)d_in[2];
    const float* bias = (const float*)d_in[3];
    float* out = (float*)d_out;

    cudaFuncSetAttribute(gptq_gemm_kernel,
                         cudaFuncAttributeMaxDynamicSharedMemorySize, SMEM_TOTAL);

    prep_kernel<<<12288, 256>>>((const float4*)x, (const int4*)qw, sc);

    dim3 grid(4096 / BN, 8192 / BM);   // (32, 64) = 2048 CTAs, 2/SM
    gptq_gemm_kernel<<<grid, THREADS, SMEM_TOTAL>>>(bias, out);
}

// round 16
// speedup vs baseline: 1.2075x; 1.0773x over previous
#include <cuda_runtime.h>
#include <cuda_fp16.h>
#include <cstdint>

// GPTQ group-quantized linear:  out[m,o] = sum_k x[m,k] * (qw[o,k]*sc[o,k/128]) + bias[o]
// M=8192, N=4096, K=4096  (275 GFLOP GEMM)
//
// Plain sm_103 PTX (no 'a') -> no tcgen05. mma.sync.m16n8k16 + cp.async + ldmatrix.
//
//   1) prep:  fused (x fp32->fp16) + (qweight*scale->fp16), 4x ILP
//   2) GEMM:  CTA 128x128x64, 3-stage ring, 2 CTAs/SM, R9 barrier protocol
//             (fragment double-buffer + cross-k-tile kk0 prefetch; boundary =
//             wait(0) -> sync -> load -> commit).
//   R16 delta: 4 warps/CTA (128 thr), warp tile 64x64 (2Mx2N) -> ldmatrix smem
//             traffic per SM-kt drops 33% (B fragments amortized over bigger
//             warp tiles); 256 regs/thread available at 2 CTAs/SM (no spills).

__device__ __half g_x16[33554432];   // 8192 * 4096
__device__ __half g_w16[16777216];   // 4096 * 4096

#define BM 128
#define BN 128
#define BK 64
#define STAGES 3
#define A_STAGE_BYTES (BM * 128)
#define B_STAGE_BYTES (BN * 128)
#define STAGE_BYTES   (A_STAGE_BYTES + B_STAGE_BYTES)   // 32768
#define SMEM_TOTAL    (STAGES * STAGE_BYTES)            // 98304 (2 CTAs -> 192K/SM)
#define THREADS 128

__device__ __forceinline__ uint32_t smem_u32(const void* p) {
    uint32_t a;
    asm("{ .reg .u64 t; cvta.to.shared.u64 t, %1; cvt.u32.u64 %0, t; }" : "=r"(a) : "l"(p));
    return a;
}

__device__ __forceinline__ void cp16(uint32_t dst, const void* src) {
    asm volatile("cp.async.cg.shared.global [%0], [%1], 16;" :: "r"(dst), "l"(src));
}

__device__ __forceinline__ uint32_t swz(uint32_t base, int row, int kb) {
    return base + row * 128 + (kb ^ ((row & 7) << 4));
}

__device__ __forceinline__ void ldmat4(uint32_t& r0, uint32_t& r1, uint32_t& r2, uint32_t& r3,
                                       uint32_t addr) {
    asm volatile("ldmatrix.sync.aligned.m8n8.x4.shared.b16 {%0,%1,%2,%3}, [%4];"
                 : "=r"(r0), "=r"(r1), "=r"(r2), "=r"(r3) : "r"(addr));
}

__device__ __forceinline__ void mma16816(float& c0, float& c1, float& c2, float& c3,
                                         uint32_t a0, uint32_t a1, uint32_t a2, uint32_t a3,
                                         uint32_t b0, uint32_t b1) {
    asm volatile("mma.sync.aligned.m16n8k16.row.col.f32.f16.f16.f32 "
                 "{%0,%1,%2,%3}, {%4,%5,%6,%7}, {%8,%9}, {%0,%1,%2,%3};"
                 : "+f"(c0), "+f"(c1), "+f"(c2), "+f"(c3)
                 : "r"(a0), "r"(a1), "r"(a2), "r"(a3), "r"(b0), "r"(b1));
}

// load one stage: A 128 rows + B 128 rows, 8x 16B chunks per row, 128 threads
__device__ __forceinline__ void load_stage(uint32_t sb, int stage,
                                           const __half* __restrict__ xrow,
                                           const __half* __restrict__ wrow,
                                           int ktile, int tid) {
    const uint32_t sA = sb + stage * STAGE_BYTES;
    const uint32_t sB = sA + A_STAGE_BYTES;
    const char* a = (const char*)(xrow + ktile * BK);
    const char* b = (const char*)(wrow + ktile * BK);
#pragma unroll
    for (int i = 0; i < 8; i++) {                 // A: 1024 chunks / 128 thr
        int idx = tid + (i << 7);
        int row = idx >> 3, c = idx & 7;
        cp16(swz(sA, row, c << 4), a + (size_t)row * 8192 + (c << 4));
    }
#pragma unroll
    for (int i = 0; i < 8; i++) {                 // B: 1024 chunks / 128 thr
        int idx = tid + (i << 7);
        int row = idx >> 3, c = idx & 7;
        cp16(swz(sB, row, c << 4), b + (size_t)row * 8192 + (c << 4));
    }
}

// -------------------- fused prepass (4x ILP) ---------------------------------
__global__ void prep_kernel(const float4* __restrict__ x,
                            const int4* __restrict__ qw,
                            const float* __restrict__ sc) {
    const int b = blockIdx.x;
    const int tid = threadIdx.x;
    if (b < 8192) {
        const int base = b * 1024 + tid;
        float4 v[4];
#pragma unroll
        for (int j = 0; j < 4; j++) v[j] = x[base + j * 256];
#pragma unroll
        for (int j = 0; j < 4; j++) {
            __half2 a = __floats2half2_rn(v[j].x, v[j].y);
            __half2 c = __floats2half2_rn(v[j].z, v[j].w);
            uint2 r;
            r.x = *reinterpret_cast<uint32_t*>(&a);
            r.y = *reinterpret_cast<uint32_t*>(&c);
            reinterpret_cast<uint2*>(g_x16)[base + j * 256] = r;
        }
    } else {
        const int base = (b - 8192) * 1024 + tid;
        int4 q[4];
#pragma unroll
        for (int j = 0; j < 4; j++) q[j] = qw[base + j * 256];
#pragma unroll
        for (int j = 0; j < 4; j++) {
            const int i = base + j * 256;
            const int k4 = i & 1023;
            const int o  = i >> 10;
            const float s = __ldg(sc + o * 32 + (k4 >> 5));
            __half2 a = __floats2half2_rn((float)q[j].x * s, (float)q[j].y * s);
            __half2 c = __floats2half2_rn((float)q[j].z * s, (float)q[j].w * s);
            uint2 r;
            r.x = *reinterpret_cast<uint32_t*>(&a);
            r.y = *reinterpret_cast<uint32_t*>(&c);
            reinterpret_cast<uint2*>(g_w16)[i] = r;
        }
    }
}

// -------------------- GEMM kernel --------------------------------------------
__global__ __launch_bounds__(THREADS, 2)
void gptq_gemm_kernel(const float* __restrict__ bias, float* __restrict__ out) {
    extern __shared__ char smem[];
    const uint32_t sb = smem_u32(smem);
    const int tid = threadIdx.x;
    const int wid = tid >> 5;
    const int lid = tid & 31;
    const int m0 = blockIdx.y * BM;
    const int n0 = blockIdx.x * BN;

    // warp layout: 2 (M) x 2 (N); warp tile 64 x 64
    const int warp_m = (wid & 1) * 64;
    const int warp_n = (wid >> 1) * 64;

    const int g = lid >> 3, w = lid & 7;
    const int a_row = (g & 1) * 8 + w;
    const int a_kb  = (g >> 1) * 16;
    const int b_row = (g >> 1) * 8 + w;
    const int b_kb  = (g & 1) * 16;

    const __half* xrow = g_x16 + (size_t)m0 * 4096;
    const __half* wrow = g_w16 + (size_t)n0 * 4096;

    float acc[4][8][4];
#pragma unroll
    for (int i = 0; i < 4; i++)
#pragma unroll
        for (int j = 0; j < 8; j++)
#pragma unroll
            for (int r = 0; r < 4; r++) acc[i][j][r] = 0.0f;

    // prologue: fill ALL 3 stages
#pragma unroll
    for (int s = 0; s < STAGES; s++) {
        load_stage(sb, s, xrow, wrow, s, tid);
        asm volatile("cp.async.commit_group;" ::: "memory");
    }
    asm volatile("cp.async.wait_group 1;" ::: "memory");
    __syncthreads();

    // fragment double-buffers
    uint32_t af[2][4][4];
    uint32_t bf[2][8][2];

    // prefetch kk0 of stage 0
    {
        const uint32_t sA = sb;
        const uint32_t sB = sA + A_STAGE_BYTES;
#pragma unroll
        for (int mt = 0; mt < 4; mt++)
            ldmat4(af[0][mt][0], af[0][mt][1], af[0][mt][2], af[0][mt][3],
                   swz(sA, warp_m + mt * 16 + a_row, a_kb));
#pragma unroll
        for (int nt2 = 0; nt2 < 4; nt2++) {
            uint32_t r0, r1, r2, r3;
            ldmat4(r0, r1, r2, r3, swz(sB, warp_n + nt2 * 16 + b_row, b_kb));
            bf[0][nt2 * 2 + 0][0] = r0; bf[0][nt2 * 2 + 0][1] = r1;
            bf[0][nt2 * 2 + 1][0] = r2; bf[0][nt2 * 2 + 1][1] = r3;
        }
    }

    const int NKT = 4096 / BK;   // 64
    int stage = 0;
    for (int kt = 0; kt < NKT; kt++) {
        const uint32_t sA = sb + stage * STAGE_BYTES;
        const uint32_t sB = sA + A_STAGE_BYTES;
        int nstage = stage + 1; if (nstage == STAGES) nstage = 0;
        const uint32_t nsA = sb + nstage * STAGE_BYTES;
        const uint32_t nsB = nsA + A_STAGE_BYTES;

#pragma unroll
        for (int kk = 0; kk < 4; kk++) {
            const int cur = kk & 1;
            const int nxt = cur ^ 1;
            if (kk < 3) {
                // prefetch kk+1 of current stage
                const int kb = (kk + 1) * 32;
#pragma unroll
                for (int mt = 0; mt < 4; mt++)
                    ldmat4(af[nxt][mt][0], af[nxt][mt][1], af[nxt][mt][2], af[nxt][mt][3],
                           swz(sA, warp_m + mt * 16 + a_row, kb + a_kb));
#pragma unroll
                for (int nt2 = 0; nt2 < 4; nt2++) {
                    uint32_t r0, r1, r2, r3;
                    ldmat4(r0, r1, r2, r3, swz(sB, warp_n + nt2 * 16 + b_row, kb + b_kb));
                    bf[nxt][nt2 * 2 + 0][0] = r0; bf[nxt][nt2 * 2 + 0][1] = r1;
                    bf[nxt][nt2 * 2 + 1][0] = r2; bf[nxt][nt2 * 2 + 1][1] = r3;
                }
            } else if (kt + 1 < NKT) {
                // prefetch kk0 of NEXT stage (proven complete at previous boundary)
#pragma unroll
                for (int mt = 0; mt < 4; mt++)
                    ldmat4(af[nxt][mt][0], af[nxt][mt][1], af[nxt][mt][2], af[nxt][mt][3],
                           swz(nsA, warp_m + mt * 16 + a_row, a_kb));
#pragma unroll
                for (int nt2 = 0; nt2 < 4; nt2++) {
                    uint32_t r0, r1, r2, r3;
                    ldmat4(r0, r1, r2, r3, swz(nsB, warp_n + nt2 * 16 + b_row, b_kb));
                    bf[nxt][nt2 * 2 + 0][0] = r0; bf[nxt][nt2 * 2 + 0][1] = r1;
                    bf[nxt][nt2 * 2 + 1][0] = r2; bf[nxt][nt2 * 2 + 1][1] = r3;
                }
            }
#pragma unroll
            for (int mt = 0; mt < 4; mt++)
#pragma unroll
                for (int nt = 0; nt < 8; nt++)
                    mma16816(acc[mt][nt][0], acc[mt][nt][1], acc[mt][nt][2], acc[mt][nt][3],
                             af[cur][mt][0], af[cur][mt][1], af[cur][mt][2], af[cur][mt][3],
                             bf[cur][nt][0], bf[cur][nt][1]);
        }

        // boundary: prove stage kt+2 complete, then recycle stage kt's buffer
        asm volatile("cp.async.wait_group 0;" ::: "memory");
        __syncthreads();
        if (kt + STAGES < NKT)
            load_stage(sb, stage, xrow, wrow, kt + STAGES, tid);
        asm volatile("cp.async.commit_group;" ::: "memory");

        stage = nstage;
    }

    // -------- epilogue -------------------------------------------------------
    const int qr = lid >> 2;
    const int qc = (lid & 3) * 2;
#pragma unroll
    for (int mt = 0; mt < 4; mt++) {
        const int row0 = m0 + warp_m + mt * 16 + qr;
#pragma unroll
        for (int nt = 0; nt < 8; nt++) {
            const int col = n0 + warp_n + nt * 8 + qc;
            const float2 bv = *reinterpret_cast<const float2*>(bias + col);
            float2 v0, v1;
            v0.x = acc[mt][nt][0] + bv.x;
            v0.y = acc[mt][nt][1] + bv.y;
            v1.x = acc[mt][nt][2] + bv.x;
            v1.y = acc[mt][nt][3] + bv.y;
            *reinterpret_cast<float2*>(out + (size_t)row0 * 4096 + col) = v0;
            *reinterpret_cast<float2*>(out + (size_t)(row0 + 8) * 4096 + col) = v1;
        }
    }
}

// -------------------- launch --------------------------------------------------
extern "C" void kernel_launch(void* const* d_in, const int* in_sizes, int n_in,
                              void* d_out, int out_size) {
    const float* x    = (const float*)d_in[0];
    const int*   qw   = (const int*)d_in[1];
    const float* sc   = (const float*)d_in[2];
    const float* bias = (const float*)d_in[3];
    float* out = (float*)d_out;

    cudaFuncSetAttribute(gptq_gemm_kernel,
                         cudaFuncAttributeMaxDynamicSharedMemorySize, SMEM_TOTAL);

    prep_kernel<<<12288, 256>>>((const float4*)x, (const int4*)qw, sc);

    dim3 grid(4096 / BN, 8192 / BM);   // (32, 64) = 2048 CTAs, 2/SM
    gptq_gemm_kernel<<<grid, THREADS, SMEM_TOTAL>>>(bias, out);
}